// round 10
// baseline (speedup 1.0000x reference)
#include <cuda_runtime.h>
#include <math.h>

typedef unsigned long long ull;

// Problem dims
#define BB 64
#define NN 133
#define NROW (BB*NN)
#define F0 75
#define F1 150
#define H1 256
#define H2 128
#define GP1 152           // padded emb output stride
#define GP3 76            // padded gc3 output stride

// ---------------- scratch ----------------
__device__ float g_bufA[(size_t)NROW * 256];
__device__ float g_bufB[(size_t)NROW * 256];

__device__ float g_embw[F0 * GP1];   // emb_w padded [75,152]
__device__ float g_embb[GP1];
__device__ float g_gc3w[H2 * GP3];   // gc3_w padded [128,76]
__device__ float g_b3pad[GP3];

__device__ int   g_nz_cnt[NROW];
__device__ ull   g_nz[(size_t)NROW * NN];      // packed {val:hi32, idx:lo32}
__device__ int   g_pl_cnt[NROW];
__device__ int   g_pl_idx[(size_t)NROW * NN];

// ---------------- f32x2 helpers (sparse kernels only) ----------------
__device__ __forceinline__ ull pk2(float x, float y) {
    ull r;
    asm("mov.b64 %0, {%1, %2};" : "=l"(r) : "f"(x), "f"(y));
    return r;
}
__device__ __forceinline__ void upk2(ull v, float& x, float& y) {
    asm("mov.b64 {%0, %1}, %2;" : "=f"(x), "=f"(y) : "l"(v));
}
#define FMA2(acc, a, b) asm("fma.rn.f32x2 %0, %1, %2, %0;" : "+l"(acc) : "l"(a), "l"(b))

// ---------------- one-time weight padding ----------------
#define PAD_T0 (F0*GP1)
#define PAD_T1 (PAD_T0 + GP1)
#define PAD_T2 (PAD_T1 + H2*GP3)
#define PAD_T3 (PAD_T2 + GP3)
__global__ void k_pad(const float* __restrict__ emb_w, const float* __restrict__ emb_b,
                      const float* __restrict__ gc3_w, const float* __restrict__ gc3_b) {
    int idx = blockIdx.x * blockDim.x + threadIdx.x;
    if (idx < PAD_T0) {
        int k = idx / GP1, g = idx % GP1;
        g_embw[idx] = (g < F1) ? emb_w[k * F1 + g] : 0.0f;
    } else if (idx < PAD_T1) {
        int g = idx - PAD_T0;
        g_embb[g] = (g < F1) ? emb_b[g] : 0.0f;
    } else if (idx < PAD_T2) {
        int j = idx - PAD_T1;
        int k = j / GP3, g = j % GP3;
        g_gc3w[j] = (g < F0) ? gc3_w[k * F0 + g] : 0.0f;
    } else if (idx < PAD_T3) {
        int g = idx - PAD_T2;
        g_b3pad[g] = (g < F0) ? gc3_b[g] : 0.0f;
    }
}

// ---------------- build sparse lists from adj (warp per row) ----------------
__global__ void k_build_lists(const float* __restrict__ adj) {
    int warp_in_blk = threadIdx.x >> 5;
    int lane = threadIdx.x & 31;
    int wg = blockIdx.x * (blockDim.x >> 5) + warp_in_blk;
    if (wg >= NROW) return;
    const float* arow = adj + (size_t)wg * NN;

    int cnz = 0, cpl = 0;
    unsigned lt = (1u << lane) - 1u;
    for (int base = 0; base < NN; base += 32) {
        int j = base + lane;
        float a = (j < NN) ? arow[j] : 0.0f;
        bool nz = (j < NN) && (a != 0.0f);
        bool pl = (j < NN) && (a > 1e-5f);
        unsigned mnz = __ballot_sync(0xffffffffu, nz);
        unsigned mpl = __ballot_sync(0xffffffffu, pl);
        if (nz) {
            int pos = cnz + __popc(mnz & lt);
            g_nz[(size_t)wg * NN + pos] =
                ((ull)__float_as_uint(a) << 32) | (unsigned)j;
        }
        if (pl) {
            int pos = cpl + __popc(mpl & lt);
            g_pl_idx[(size_t)wg * NN + pos] = j;
        }
        cnz += __popc(mnz);
        cpl += __popc(mpl);
    }
    if (lane == 0) { g_nz_cnt[wg] = cnz; g_pl_cnt[wg] = cpl; }
}

// ---------------- dense GEMM: smem-staged W, R rows x 4 cols/thread ---------
// C[b,i,g] = A[b,i,:] @ W[:,g] (+bias, relu).
// grid (ceil(133/(R*RG)), 64), block (G/4, RG). Small R => many warps (occ).
template<int R>
__global__ void k_dense_st(const float* __restrict__ A, const float* __restrict__ W,
                           const float* __restrict__ bias, float* __restrict__ C,
                           int K, int AS, int G, int GP, int do_relu) {
    const int KC = 32;
    extern __shared__ float sm[];
    int BN = blockDim.x * 4;                 // == G
    float* sW = sm;                          // [KC][BN]
    float* sA = sm + KC * BN;                // [nrows][KC]

    int b     = blockIdx.y;
    int nrows = R * blockDim.y;
    int rows0 = blockIdx.x * nrows;
    int tid   = threadIdx.y * blockDim.x + threadIdx.x;
    int nthr  = blockDim.x * blockDim.y;
    int g0    = threadIdx.x * 4;

    float acc[R][4];
    #pragma unroll
    for (int r = 0; r < R; r++)
        #pragma unroll
        for (int c = 0; c < 4; c++) acc[r][c] = 0.0f;

    for (int kc = 0; kc < K; kc += KC) {
        // fill sW (float4 coalesced LDG, stride-1 STS.128)
        for (int kk = threadIdx.y; kk < KC; kk += blockDim.y) {
            int k = kc + kk;
            float4 w = make_float4(0.f, 0.f, 0.f, 0.f);
            if (k < K) w = *reinterpret_cast<const float4*>(W + (size_t)k * G + g0);
            *reinterpret_cast<float4*>(sW + kk * BN + g0) = w;
        }
        // fill sA (consecutive tid -> consecutive kk: coalesced)
        for (int idx = tid; idx < nrows * KC; idx += nthr) {
            int r = idx >> 5, kk = idx & 31;
            int row = rows0 + r;
            int k = kc + kk;
            sA[idx] = (row < NN && k < K) ? A[(size_t)(b * NN + row) * AS + k] : 0.0f;
        }
        __syncthreads();

        const float* sAr = sA + threadIdx.y * R * KC;
        #pragma unroll 8
        for (int kk = 0; kk < KC; kk++) {
            float4 w = *reinterpret_cast<const float4*>(sW + kk * BN + g0);
            #pragma unroll
            for (int r = 0; r < R; r++) {
                float a = sAr[r * KC + kk];          // warp broadcast
                acc[r][0] = fmaf(a, w.x, acc[r][0]);
                acc[r][1] = fmaf(a, w.y, acc[r][1]);
                acc[r][2] = fmaf(a, w.z, acc[r][2]);
                acc[r][3] = fmaf(a, w.w, acc[r][3]);
            }
        }
        __syncthreads();
    }

    float4 bv = make_float4(0.f, 0.f, 0.f, 0.f);
    if (bias) bv = *reinterpret_cast<const float4*>(bias + g0);
    int i0 = threadIdx.y * R;
    #pragma unroll
    for (int r = 0; r < R; r++) {
        int row = rows0 + i0 + r;
        if (row >= NN) continue;
        float4 v = make_float4(acc[r][0] + bv.x, acc[r][1] + bv.y,
                               acc[r][2] + bv.z, acc[r][3] + bv.w);
        if (do_relu) {
            v.x = fmaxf(v.x, 0.f); v.y = fmaxf(v.y, 0.f);
            v.z = fmaxf(v.z, 0.f); v.w = fmaxf(v.w, 0.f);
        }
        *reinterpret_cast<float4*>(C + (size_t)(b * NN + row) * GP + g0) = v;
    }
}

// ---------------- spmm + relu, 4 cols/thread, 4-edge unrolled gather --------
__global__ void k_spmm4(const float* __restrict__ T, const float* __restrict__ bias,
                        float* __restrict__ O, int G) {
    int b = blockIdx.y;
    int i = blockIdx.x * blockDim.y + threadIdx.y;
    if (i >= NN) return;
    int row = b * NN + i;
    int g0 = threadIdx.x * 4;

    int cnt = g_nz_cnt[row];
    const ull* L = g_nz + (size_t)row * NN;
    const float* Tb = T + (size_t)b * NN * G + g0;

    ull acc0 = pk2(bias[g0], bias[g0 + 1]);
    ull acc1 = pk2(bias[g0 + 2], bias[g0 + 3]);
    int e = 0;
    for (; e + 4 <= cnt; e += 4) {
        ull p0 = L[e], p1 = L[e + 1], p2 = L[e + 2], p3 = L[e + 3];
        ulonglong2 t0 = *(const ulonglong2*)(Tb + (size_t)(unsigned)p0 * G);
        ulonglong2 t1 = *(const ulonglong2*)(Tb + (size_t)(unsigned)p1 * G);
        ulonglong2 t2 = *(const ulonglong2*)(Tb + (size_t)(unsigned)p2 * G);
        ulonglong2 t3 = *(const ulonglong2*)(Tb + (size_t)(unsigned)p3 * G);
        float v0 = __uint_as_float((unsigned)(p0 >> 32));
        float v1 = __uint_as_float((unsigned)(p1 >> 32));
        float v2 = __uint_as_float((unsigned)(p2 >> 32));
        float v3 = __uint_as_float((unsigned)(p3 >> 32));
        FMA2(acc0, t0.x, pk2(v0, v0)); FMA2(acc1, t0.y, pk2(v0, v0));
        FMA2(acc0, t1.x, pk2(v1, v1)); FMA2(acc1, t1.y, pk2(v1, v1));
        FMA2(acc0, t2.x, pk2(v2, v2)); FMA2(acc1, t2.y, pk2(v2, v2));
        FMA2(acc0, t3.x, pk2(v3, v3)); FMA2(acc1, t3.y, pk2(v3, v3));
    }
    for (; e < cnt; e++) {
        ull p0 = L[e];
        ulonglong2 t0 = *(const ulonglong2*)(Tb + (size_t)(unsigned)p0 * G);
        float v0 = __uint_as_float((unsigned)(p0 >> 32));
        FMA2(acc0, t0.x, pk2(v0, v0));
        FMA2(acc1, t0.y, pk2(v0, v0));
    }
    float h0, h1, h2, h3;
    upk2(acc0, h0, h1);
    upk2(acc1, h2, h3);
    float4 r = make_float4(fmaxf(h0, 0.f), fmaxf(h1, 0.f), fmaxf(h2, 0.f), fmaxf(h3, 0.f));
    *reinterpret_cast<float4*>(O + (size_t)row * G + g0) = r;
}

// ---------------- neighbor max-pool, 4 cols/thread, 4-edge unrolled ---------
__global__ void k_pool4(const float* __restrict__ H, float* __restrict__ O, int G) {
    int b = blockIdx.y;
    int i = blockIdx.x * blockDim.y + threadIdx.y;
    if (i >= NN) return;
    int row = b * NN + i;
    int g0 = threadIdx.x * 4;

    int cnt = g_pl_cnt[row];
    const int* ji = g_pl_idx + (size_t)row * NN;
    const float4* Hb = reinterpret_cast<const float4*>(H + (size_t)b * NN * G + g0);
    int pitch = G >> 2;

    float4 m = make_float4(0.f, 0.f, 0.f, 0.f);   // H >= 0 post-relu
    int e = 0;
    for (; e + 4 <= cnt; e += 4) {
        int j0 = ji[e], j1 = ji[e + 1], j2 = ji[e + 2], j3 = ji[e + 3];
        float4 h0 = Hb[(size_t)j0 * pitch];
        float4 h1 = Hb[(size_t)j1 * pitch];
        float4 h2 = Hb[(size_t)j2 * pitch];
        float4 h3 = Hb[(size_t)j3 * pitch];
        m.x = fmaxf(m.x, fmaxf(fmaxf(h0.x, h1.x), fmaxf(h2.x, h3.x)));
        m.y = fmaxf(m.y, fmaxf(fmaxf(h0.y, h1.y), fmaxf(h2.y, h3.y)));
        m.z = fmaxf(m.z, fmaxf(fmaxf(h0.z, h1.z), fmaxf(h2.z, h3.z)));
        m.w = fmaxf(m.w, fmaxf(fmaxf(h0.w, h1.w), fmaxf(h2.w, h3.w)));
    }
    for (; e < cnt; e++) {
        float4 h0 = Hb[(size_t)ji[e] * pitch];
        m.x = fmaxf(m.x, h0.x); m.y = fmaxf(m.y, h0.y);
        m.z = fmaxf(m.z, h0.z); m.w = fmaxf(m.w, h0.w);
    }
    reinterpret_cast<float4*>(O + (size_t)row * G + g0)[0] = m;
}

// ---------------- head: gc4 + fc1 + fin + sigmoid ----------
__global__ void k_final(const float* __restrict__ P3,
                        const float* __restrict__ gc4_w,
                        const float* __restrict__ gc4_b,
                        const float* __restrict__ fc1_w,
                        const float* __restrict__ fc1_b,
                        const float* __restrict__ fin_w,
                        const float* __restrict__ fin_b,
                        float* __restrict__ out) {
    int b = blockIdx.x;
    int t = threadIdx.x;
    __shared__ float t4[NN];
    __shared__ float h[NN];
    __shared__ float rr[3];

    if (t < NN) {
        const float* p = P3 + (size_t)(b * NN + t) * GP3;
        float a = 0.0f;
        #pragma unroll
        for (int k = 0; k < F0; k++) a = fmaf(p[k], gc4_w[k], a);
        t4[t] = a;
    }
    __syncthreads();

    if (t < NN) {
        int row = b * NN + t;
        int cnt = g_nz_cnt[row];
        const ull* L = g_nz + (size_t)row * NN;
        float acc = gc4_b[0];
        for (int e = 0; e < cnt; e++) {
            ull p = L[e];
            acc = fmaf(__uint_as_float((unsigned)(p >> 32)), t4[(int)(unsigned)p], acc);
        }
        h[t] = fmaxf(acc, 0.0f);
    }
    __syncthreads();

    if (t < 3) {
        float a = fc1_b[t];
        for (int k = 0; k < NN - 1; k++)
            a = fmaf(h[k + 1], fc1_w[k * 3 + t], a);
        rr[t] = a;
    }
    __syncthreads();

    if (t == 0) {
        float z = h[0] * fin_w[0] + rr[0] * fin_w[1] + rr[1] * fin_w[2]
                + rr[2] * fin_w[3] + fin_b[0];
        out[b] = 1.0f / (1.0f + expf(-z));
    }
}

// ---------------- launch ----------------
extern "C" void kernel_launch(void* const* d_in, const int* in_sizes, int n_in,
                              void* d_out, int out_size) {
    const float* x     = (const float*)d_in[0];
    const float* adj   = (const float*)d_in[1];
    const float* emb_w = (const float*)d_in[2];
    const float* emb_b = (const float*)d_in[3];
    const float* gc1_w = (const float*)d_in[4];
    const float* gc1_b = (const float*)d_in[5];
    const float* gc2_w = (const float*)d_in[6];
    const float* gc2_b = (const float*)d_in[7];
    const float* gc3_w = (const float*)d_in[8];
    const float* gc3_b = (const float*)d_in[9];
    const float* gc4_w = (const float*)d_in[10];
    const float* gc4_b = (const float*)d_in[11];
    const float* fc1_w = (const float*)d_in[12];
    const float* fc1_b = (const float*)d_in[13];
    const float* fin_w = (const float*)d_in[14];
    const float* fin_b = (const float*)d_in[15];
    float* out = (float*)d_out;

    float *dA, *dB, *dEw, *dEb, *d3w, *db3;
    cudaGetSymbolAddress((void**)&dA,  g_bufA);
    cudaGetSymbolAddress((void**)&dB,  g_bufB);
    cudaGetSymbolAddress((void**)&dEw, g_embw);
    cudaGetSymbolAddress((void**)&dEb, g_embb);
    cudaGetSymbolAddress((void**)&d3w, g_gc3w);
    cudaGetSymbolAddress((void**)&db3, g_b3pad);

    // 0a) pad weights (emb, gc3)
    k_pad<<<(PAD_T3 + 255) / 256, 256>>>(emb_w, emb_b, gc3_w, gc3_b);
    // 0b) sparse lists
    {
        int warps_per_blk = 8;
        int blocks = (NROW + warps_per_blk - 1) / warps_per_blk;
        k_build_lists<<<blocks, warps_per_blk * 32>>>(adj);
    }

    const int KC = 32;
    // smem bytes: KC*G*4 + nrows*KC*4
    int sm_emb = (KC * GP1 + 12 * KC) * 4;   // R=2, RG=6  -> 12 rows
    int sm_gc1 = (KC * H1  +  8 * KC) * 4;   // R=2, RG=4  ->  8 rows
    int sm_gc2 = (KC * H2  + 16 * KC) * 4;   // R=2, RG=8  -> 16 rows
    int sm_gc3 = (KC * GP3 + 13 * KC) * 4;   // R=1, RG=13 -> 13 rows

    // 1) emb: dA = relu(x @ embw_pad + embb_pad)   [.,152]
    k_dense_st<2><<<dim3(12, BB), dim3(38, 6), sm_emb>>>(x, dEw, dEb, dA, F0, F0, GP1, GP1, 1);
    // 2) dB = dA @ gc1_w                           [.,256]  (A stride 152, K=150)
    k_dense_st<2><<<dim3(17, BB), dim3(64, 4), sm_gc1>>>(dA, gc1_w, nullptr, dB, F1, GP1, H1, H1, 0);
    // 3) dA = relu(adj.dB + gc1_b)
    k_spmm4<<<dim3(34, BB), dim3(64, 4)>>>(dB, gc1_b, dA, H1);
    // 4) dB = pool(dA)
    k_pool4<<<dim3(34, BB), dim3(64, 4)>>>(dA, dB, H1);
    // 5) dA = dB @ gc2_w                           [.,128]
    k_dense_st<2><<<dim3(9, BB), dim3(32, 8), sm_gc2>>>(dB, gc2_w, nullptr, dA, H1, H1, H2, H2, 0);
    // 6) dB = relu(adj.dA + gc2_b)
    k_spmm4<<<dim3(17, BB), dim3(32, 8)>>>(dA, gc2_b, dB, H2);
    // 7) dA = pool(dB)
    k_pool4<<<dim3(17, BB), dim3(32, 8)>>>(dB, dA, H2);
    // 8) dB = dA @ gc3w_pad                        [.,76]
    k_dense_st<1><<<dim3(11, BB), dim3(19, 13), sm_gc3>>>(dA, d3w, nullptr, dB, H2, H2, GP3, GP3, 0);
    // 9) dA = relu(adj.dB + b3pad)                 [.,76]
    k_spmm4<<<dim3(17, BB), dim3(19, 8)>>>(dB, db3, dA, GP3);
    // 10) dB = pool(dA)                            [.,76]
    k_pool4<<<dim3(17, BB), dim3(19, 8)>>>(dA, dB, GP3);
    // 11) head
    k_final<<<BB, 160>>>(dB, gc4_w, gc4_b, fc1_w, fc1_b, fin_w, fin_b, out);
}

// round 11
// speedup vs baseline: 1.2948x; 1.2948x over previous
#include <cuda_runtime.h>
#include <math.h>

typedef unsigned long long ull;

// Problem dims
#define BB 64
#define NN 133
#define NROW (BB*NN)      // 8512 (flattened M; 8512 = 32*266 = 64*133 exactly)
#define F0 75
#define F1 150
#define H1 256
#define H2 128
#define GP1 152           // padded emb output stride
#define GP3 76            // padded gc3 output stride
#define LSTR 136          // edge-list stride (>= roundup8(133))

// ---------------- scratch ----------------
__device__ float g_bufA[(size_t)NROW * 256];
__device__ float g_bufB[(size_t)NROW * 256];

__device__ float g_embw[F0 * GP1];   // emb_w padded [75,152]
__device__ float g_embb[GP1];
__device__ float g_gc3w[H2 * GP3];   // gc3_w padded [128,76]
__device__ float g_b3pad[GP3];

__device__ int   g_nz_cnt[NROW];     // padded to multiple of 8
__device__ ull   g_nz[(size_t)NROW * LSTR];   // packed {val:hi32, idx:lo32}; pad = 0
__device__ int   g_pl_cnt[NROW];     // padded to multiple of 8
__device__ int   g_pl_idx[(size_t)NROW * LSTR]; // pad = first neighbor (dup)

// ---------------- f32x2 helpers (sparse kernels only) ----------------
__device__ __forceinline__ ull pk2(float x, float y) {
    ull r;
    asm("mov.b64 %0, {%1, %2};" : "=l"(r) : "f"(x), "f"(y));
    return r;
}
__device__ __forceinline__ void upk2(ull v, float& x, float& y) {
    asm("mov.b64 {%0, %1}, %2;" : "=f"(x), "=f"(y) : "l"(v));
}
#define FMA2(acc, a, b) asm("fma.rn.f32x2 %0, %1, %2, %0;" : "+l"(acc) : "l"(a), "l"(b))

// ---------------- one-time weight padding ----------------
#define PAD_T0 (F0*GP1)
#define PAD_T1 (PAD_T0 + GP1)
#define PAD_T2 (PAD_T1 + H2*GP3)
#define PAD_T3 (PAD_T2 + GP3)
__global__ void k_pad(const float* __restrict__ emb_w, const float* __restrict__ emb_b,
                      const float* __restrict__ gc3_w, const float* __restrict__ gc3_b) {
    int idx = blockIdx.x * blockDim.x + threadIdx.x;
    if (idx < PAD_T0) {
        int k = idx / GP1, g = idx % GP1;
        g_embw[idx] = (g < F1) ? emb_w[k * F1 + g] : 0.0f;
    } else if (idx < PAD_T1) {
        int g = idx - PAD_T0;
        g_embb[g] = (g < F1) ? emb_b[g] : 0.0f;
    } else if (idx < PAD_T2) {
        int j = idx - PAD_T1;
        int k = j / GP3, g = j % GP3;
        g_gc3w[j] = (g < F0) ? gc3_w[k * F0 + g] : 0.0f;
    } else if (idx < PAD_T3) {
        int g = idx - PAD_T2;
        g_b3pad[g] = (g < F0) ? gc3_b[g] : 0.0f;
    }
}

// ---------------- build sparse lists (warp per row), 8-padded ----------------
__global__ void k_build_lists(const float* __restrict__ adj) {
    int warp_in_blk = threadIdx.x >> 5;
    int lane = threadIdx.x & 31;
    int wg = blockIdx.x * (blockDim.x >> 5) + warp_in_blk;
    if (wg >= NROW) return;
    const float* arow = adj + (size_t)wg * NN;

    int cnz = 0, cpl = 0;
    int firstj = 0;
    unsigned lt = (1u << lane) - 1u;
    for (int base = 0; base < NN; base += 32) {
        int j = base + lane;
        float a = (j < NN) ? arow[j] : 0.0f;
        bool nz = (j < NN) && (a != 0.0f);
        bool pl = (j < NN) && (a > 1e-5f);
        unsigned mnz = __ballot_sync(0xffffffffu, nz);
        unsigned mpl = __ballot_sync(0xffffffffu, pl);
        if (nz) {
            int pos = cnz + __popc(mnz & lt);
            g_nz[(size_t)wg * LSTR + pos] =
                ((ull)__float_as_uint(a) << 32) | (unsigned)j;
        }
        if (pl) {
            int pos = cpl + __popc(mpl & lt);
            g_pl_idx[(size_t)wg * LSTR + pos] = j;
        }
        if (cpl == 0 && mpl) firstj = base + __ffs(mpl) - 1;
        cnz += __popc(mnz);
        cpl += __popc(mpl);
    }
    int pnz = (cnz + 7) & ~7;
    int ppl = (cpl + 7) & ~7;
    // pad spmm list with zeros (0*anything accumulates 0)
    if (lane < pnz - cnz) g_nz[(size_t)wg * LSTR + cnz + lane] = 0ull;
    // pad pool list with duplicate of first neighbor (max unchanged)
    if (lane < ppl - cpl) g_pl_idx[(size_t)wg * LSTR + cpl + lane] = firstj;
    if (lane == 0) { g_nz_cnt[wg] = pnz; g_pl_cnt[wg] = ppl; }
}

// ---------------- dense GEMM: flat M, smem W+A, R rows x 4 cols/thread ------
// C[m,g] = A[m,:] @ W[:,g] (+bias, relu); m = 0..8511 flattened.
// grid (8512/(R*RG)), block (G/4, RG). Balanced crossbar/FFMA at R=4.
template<int R>
__global__ void k_dense_f(const float* __restrict__ A, const float* __restrict__ W,
                          const float* __restrict__ bias, float* __restrict__ C,
                          int K, int AS, int G, int GP, int do_relu) {
    const int KC = 32;
    extern __shared__ float sm[];
    int BN = blockDim.x * 4;                 // == G
    float* sW = sm;                          // [KC][BN]
    float* sA = sm + KC * BN;                // [nrows][KC]

    int nrows = R * blockDim.y;
    int m0    = blockIdx.x * nrows;          // grid divides 8512 exactly
    int tid   = threadIdx.y * blockDim.x + threadIdx.x;
    int nthr  = blockDim.x * blockDim.y;
    int g0    = threadIdx.x * 4;

    float acc[R][4];
    #pragma unroll
    for (int r = 0; r < R; r++)
        #pragma unroll
        for (int c = 0; c < 4; c++) acc[r][c] = 0.0f;

    for (int kc = 0; kc < K; kc += KC) {
        for (int kk = threadIdx.y; kk < KC; kk += blockDim.y) {
            int k = kc + kk;
            float4 w = make_float4(0.f, 0.f, 0.f, 0.f);
            if (k < K) w = *reinterpret_cast<const float4*>(W + (size_t)k * G + g0);
            *reinterpret_cast<float4*>(sW + kk * BN + g0) = w;
        }
        for (int idx = tid; idx < nrows * KC; idx += nthr) {
            int r = idx >> 5, kk = idx & 31;
            int k = kc + kk;
            sA[idx] = (k < K) ? A[(size_t)(m0 + r) * AS + k] : 0.0f;
        }
        __syncthreads();

        const float* sAr = sA + threadIdx.y * R * KC;
        #pragma unroll 8
        for (int kk = 0; kk < KC; kk++) {
            float4 w = *reinterpret_cast<const float4*>(sW + kk * BN + g0);
            #pragma unroll
            for (int r = 0; r < R; r++) {
                float a = sAr[r * KC + kk];          // warp broadcast
                acc[r][0] = fmaf(a, w.x, acc[r][0]);
                acc[r][1] = fmaf(a, w.y, acc[r][1]);
                acc[r][2] = fmaf(a, w.z, acc[r][2]);
                acc[r][3] = fmaf(a, w.w, acc[r][3]);
            }
        }
        __syncthreads();
    }

    float4 bv = make_float4(0.f, 0.f, 0.f, 0.f);
    if (bias) bv = *reinterpret_cast<const float4*>(bias + g0);
    int i0 = threadIdx.y * R;
    #pragma unroll
    for (int r = 0; r < R; r++) {
        int row = m0 + i0 + r;
        float4 v = make_float4(acc[r][0] + bv.x, acc[r][1] + bv.y,
                               acc[r][2] + bv.z, acc[r][3] + bv.w);
        if (do_relu) {
            v.x = fmaxf(v.x, 0.f); v.y = fmaxf(v.y, 0.f);
            v.z = fmaxf(v.z, 0.f); v.w = fmaxf(v.w, 0.f);
        }
        *reinterpret_cast<float4*>(C + (size_t)row * GP + g0) = v;
    }
}

// ---------------- spmm + relu, 4 cols/thread, 8-deep gather (no remainder) --
__global__ void k_spmm4(const float* __restrict__ T, const float* __restrict__ bias,
                        float* __restrict__ O, int G) {
    int b = blockIdx.y;
    int i = blockIdx.x * blockDim.y + threadIdx.y;
    if (i >= NN) return;
    int row = b * NN + i;
    int g0 = threadIdx.x * 4;

    int cnt = g_nz_cnt[row];                 // multiple of 8
    const ull* L = g_nz + (size_t)row * LSTR;
    const float* Tb = T + (size_t)b * NN * G + g0;

    ull acc0 = pk2(bias[g0], bias[g0 + 1]);
    ull acc1 = pk2(bias[g0 + 2], bias[g0 + 3]);
    for (int e = 0; e < cnt; e += 8) {
        ull p[8];
        #pragma unroll
        for (int u = 0; u < 8; u++) p[u] = L[e + u];
        ulonglong2 t[8];
        #pragma unroll
        for (int u = 0; u < 8; u++)
            t[u] = *(const ulonglong2*)(Tb + (size_t)(unsigned)p[u] * G);
        #pragma unroll
        for (int u = 0; u < 8; u++) {
            float v = __uint_as_float((unsigned)(p[u] >> 32));
            ull v2 = pk2(v, v);
            FMA2(acc0, t[u].x, v2);
            FMA2(acc1, t[u].y, v2);
        }
    }
    float h0, h1, h2, h3;
    upk2(acc0, h0, h1);
    upk2(acc1, h2, h3);
    float4 r = make_float4(fmaxf(h0, 0.f), fmaxf(h1, 0.f), fmaxf(h2, 0.f), fmaxf(h3, 0.f));
    *reinterpret_cast<float4*>(O + (size_t)row * G + g0) = r;
}

// ---------------- neighbor max-pool, 4 cols/thread, 8-deep (no remainder) ---
__global__ void k_pool4(const float* __restrict__ H, float* __restrict__ O, int G) {
    int b = blockIdx.y;
    int i = blockIdx.x * blockDim.y + threadIdx.y;
    if (i >= NN) return;
    int row = b * NN + i;
    int g0 = threadIdx.x * 4;

    int cnt = g_pl_cnt[row];                 // multiple of 8; pads = dup first
    const int* ji = g_pl_idx + (size_t)row * LSTR;
    const float4* Hb = reinterpret_cast<const float4*>(H + (size_t)b * NN * G + g0);
    int pitch = G >> 2;

    float4 m = make_float4(0.f, 0.f, 0.f, 0.f);   // H >= 0 post-relu
    for (int e = 0; e < cnt; e += 8) {
        int j[8];
        #pragma unroll
        for (int u = 0; u < 8; u++) j[u] = ji[e + u];
        float4 h[8];
        #pragma unroll
        for (int u = 0; u < 8; u++) h[u] = Hb[(size_t)j[u] * pitch];
        #pragma unroll
        for (int u = 0; u < 8; u++) {
            m.x = fmaxf(m.x, h[u].x);
            m.y = fmaxf(m.y, h[u].y);
            m.z = fmaxf(m.z, h[u].z);
            m.w = fmaxf(m.w, h[u].w);
        }
    }
    reinterpret_cast<float4*>(O + (size_t)row * G + g0)[0] = m;
}

// ---------------- head: gc4 + fc1 + fin + sigmoid ----------
__global__ void k_final(const float* __restrict__ P3,
                        const float* __restrict__ gc4_w,
                        const float* __restrict__ gc4_b,
                        const float* __restrict__ fc1_w,
                        const float* __restrict__ fc1_b,
                        const float* __restrict__ fin_w,
                        const float* __restrict__ fin_b,
                        float* __restrict__ out) {
    int b = blockIdx.x;
    int t = threadIdx.x;
    __shared__ float t4[NN];
    __shared__ float h[NN];
    __shared__ float rr[3];

    if (t < NN) {
        const float* p = P3 + (size_t)(b * NN + t) * GP3;
        float a = 0.0f;
        #pragma unroll
        for (int k = 0; k < F0; k++) a = fmaf(p[k], gc4_w[k], a);
        t4[t] = a;
    }
    __syncthreads();

    if (t < NN) {
        int row = b * NN + t;
        int cnt = g_nz_cnt[row];             // padded; zero entries are no-ops
        const ull* L = g_nz + (size_t)row * LSTR;
        float acc = gc4_b[0];
        for (int e = 0; e < cnt; e++) {
            ull p = L[e];
            acc = fmaf(__uint_as_float((unsigned)(p >> 32)), t4[(int)(unsigned)p], acc);
        }
        h[t] = fmaxf(acc, 0.0f);
    }
    __syncthreads();

    if (t < 3) {
        float a = fc1_b[t];
        for (int k = 0; k < NN - 1; k++)
            a = fmaf(h[k + 1], fc1_w[k * 3 + t], a);
        rr[t] = a;
    }
    __syncthreads();

    if (t == 0) {
        float z = h[0] * fin_w[0] + rr[0] * fin_w[1] + rr[1] * fin_w[2]
                + rr[2] * fin_w[3] + fin_b[0];
        out[b] = 1.0f / (1.0f + expf(-z));
    }
}

// ---------------- launch ----------------
extern "C" void kernel_launch(void* const* d_in, const int* in_sizes, int n_in,
                              void* d_out, int out_size) {
    const float* x     = (const float*)d_in[0];
    const float* adj   = (const float*)d_in[1];
    const float* emb_w = (const float*)d_in[2];
    const float* emb_b = (const float*)d_in[3];
    const float* gc1_w = (const float*)d_in[4];
    const float* gc1_b = (const float*)d_in[5];
    const float* gc2_w = (const float*)d_in[6];
    const float* gc2_b = (const float*)d_in[7];
    const float* gc3_w = (const float*)d_in[8];
    const float* gc3_b = (const float*)d_in[9];
    const float* gc4_w = (const float*)d_in[10];
    const float* gc4_b = (const float*)d_in[11];
    const float* fc1_w = (const float*)d_in[12];
    const float* fc1_b = (const float*)d_in[13];
    const float* fin_w = (const float*)d_in[14];
    const float* fin_b = (const float*)d_in[15];
    float* out = (float*)d_out;

    float *dA, *dB, *dEw, *dEb, *d3w, *db3;
    cudaGetSymbolAddress((void**)&dA,  g_bufA);
    cudaGetSymbolAddress((void**)&dB,  g_bufB);
    cudaGetSymbolAddress((void**)&dEw, g_embw);
    cudaGetSymbolAddress((void**)&dEb, g_embb);
    cudaGetSymbolAddress((void**)&d3w, g_gc3w);
    cudaGetSymbolAddress((void**)&db3, g_b3pad);

    // 0a) pad weights (emb, gc3)
    k_pad<<<(PAD_T3 + 255) / 256, 256>>>(emb_w, emb_b, gc3_w, gc3_b);
    // 0b) sparse lists (8-padded)
    {
        int warps_per_blk = 8;
        int blocks = (NROW + warps_per_blk - 1) / warps_per_blk;
        k_build_lists<<<blocks, warps_per_blk * 32>>>(adj);
    }

    const int KC = 32;
    int sm_emb = (KC * GP1 + 32 * KC) * 4;   // nrows=32
    int sm_gc1 = (KC * H1  + 32 * KC) * 4;   // nrows=32
    int sm_gc2 = (KC * H2  + 64 * KC) * 4;   // nrows=64
    int sm_gc3 = (KC * GP3 + 64 * KC) * 4;   // nrows=64

    // 1) emb: dA = relu(x @ embw_pad + embb_pad)   [8512,152]
    k_dense_f<4><<<266, dim3(38, 8), sm_emb>>>(x, dEw, dEb, dA, F0, F0, GP1, GP1, 1);
    // 2) dB = dA @ gc1_w                           [8512,256] (A stride 152, K=150)
    k_dense_f<4><<<266, dim3(64, 8), sm_gc1>>>(dA, gc1_w, nullptr, dB, F1, GP1, H1, H1, 0);
    // 3) dA = relu(adj.dB + gc1_b)
    k_spmm4<<<dim3(34, BB), dim3(64, 4)>>>(dB, gc1_b, dA, H1);
    // 4) dB = pool(dA)
    k_pool4<<<dim3(34, BB), dim3(64, 4)>>>(dA, dB, H1);
    // 5) dA = dB @ gc2_w                           [8512,128]
    k_dense_f<4><<<133, dim3(32, 16), sm_gc2>>>(dB, gc2_w, nullptr, dA, H1, H1, H2, H2, 0);
    // 6) dB = relu(adj.dA + gc2_b)
    k_spmm4<<<dim3(17, BB), dim3(32, 8)>>>(dA, gc2_b, dB, H2);
    // 7) dA = pool(dB)
    k_pool4<<<dim3(17, BB), dim3(32, 8)>>>(dB, dA, H2);
    // 8) dB = dA @ gc3w_pad                        [8512,76]
    k_dense_f<4><<<133, dim3(19, 16), sm_gc3>>>(dA, d3w, nullptr, dB, H2, H2, GP3, GP3, 0);
    // 9) dA = relu(adj.dB + b3pad)                 [.,76]
    k_spmm4<<<dim3(17, BB), dim3(19, 8)>>>(dB, db3, dA, GP3);
    // 10) dB = pool(dA)                            [.,76]
    k_pool4<<<dim3(17, BB), dim3(19, 8)>>>(dA, dB, GP3);
    // 11) head
    k_final<<<BB, 160>>>(dB, gc4_w, gc4_b, fc1_w, fc1_b, fin_w, fin_b, out);
}

// round 12
// speedup vs baseline: 1.3934x; 1.0761x over previous
#include <cuda_runtime.h>
#include <math.h>

typedef unsigned long long ull;

// Problem dims
#define BB 64
#define NN 133
#define NROW (BB*NN)      // 8512 (flattened M)
#define F0 75
#define F1 150
#define H1 256
#define H2 128
#define GP1 152           // padded emb output stride
#define GP3 76            // padded gc3 output stride
#define LSTR 136          // edge-list stride

// ---------------- scratch ----------------
__device__ float g_bufA[(size_t)NROW * 256];
__device__ float g_bufB[(size_t)NROW * 256];

__device__ float g_embw[F0 * GP1];
__device__ float g_embb[GP1];
__device__ float g_gc3w[H2 * GP3];
__device__ float g_b3pad[GP3];

__device__ int   g_nz_cnt[NROW];
__device__ ull   g_nz[(size_t)NROW * LSTR];
__device__ int   g_pl_cnt[NROW];
__device__ int   g_pl_idx[(size_t)NROW * LSTR];

// ---------------- f32x2 helpers (sparse kernels only) ----------------
__device__ __forceinline__ ull pk2(float x, float y) {
    ull r;
    asm("mov.b64 %0, {%1, %2};" : "=l"(r) : "f"(x), "f"(y));
    return r;
}
__device__ __forceinline__ void upk2(ull v, float& x, float& y) {
    asm("mov.b64 {%0, %1}, %2;" : "=f"(x), "=f"(y) : "l"(v));
}
#define FMA2(acc, a, b) asm("fma.rn.f32x2 %0, %1, %2, %0;" : "+l"(acc) : "l"(a), "l"(b))

// ---------------- cp.async helpers ----------------
__device__ __forceinline__ unsigned smem_u32p(const void* p) {
    return (unsigned)__cvta_generic_to_shared(p);
}
__device__ __forceinline__ void cp16(unsigned dst, const void* src) {
    asm volatile("cp.async.ca.shared.global [%0], [%1], 16;" :: "r"(dst), "l"(src));
}
__device__ __forceinline__ void cp4(unsigned dst, const void* src) {
    asm volatile("cp.async.ca.shared.global [%0], [%1], 4;" :: "r"(dst), "l"(src));
}
__device__ __forceinline__ void cp_commit() {
    asm volatile("cp.async.commit_group;" ::: "memory");
}
template<int N>
__device__ __forceinline__ void cp_wait() {
    asm volatile("cp.async.wait_group %0;" :: "n"(N) : "memory");
}

// ---------------- one-time weight padding ----------------
#define PAD_T0 (F0*GP1)
#define PAD_T1 (PAD_T0 + GP1)
#define PAD_T2 (PAD_T1 + H2*GP3)
#define PAD_T3 (PAD_T2 + GP3)
__global__ void k_pad(const float* __restrict__ emb_w, const float* __restrict__ emb_b,
                      const float* __restrict__ gc3_w, const float* __restrict__ gc3_b) {
    int idx = blockIdx.x * blockDim.x + threadIdx.x;
    if (idx < PAD_T0) {
        int k = idx / GP1, g = idx % GP1;
        g_embw[idx] = (g < F1) ? emb_w[k * F1 + g] : 0.0f;
    } else if (idx < PAD_T1) {
        int g = idx - PAD_T0;
        g_embb[g] = (g < F1) ? emb_b[g] : 0.0f;
    } else if (idx < PAD_T2) {
        int j = idx - PAD_T1;
        int k = j / GP3, g = j % GP3;
        g_gc3w[j] = (g < F0) ? gc3_w[k * F0 + g] : 0.0f;
    } else if (idx < PAD_T3) {
        int g = idx - PAD_T2;
        g_b3pad[g] = (g < F0) ? gc3_b[g] : 0.0f;
    }
}

// ---------------- build sparse lists (warp per row), 8-padded ----------------
__global__ void k_build_lists(const float* __restrict__ adj) {
    int warp_in_blk = threadIdx.x >> 5;
    int lane = threadIdx.x & 31;
    int wg = blockIdx.x * (blockDim.x >> 5) + warp_in_blk;
    if (wg >= NROW) return;
    const float* arow = adj + (size_t)wg * NN;

    int cnz = 0, cpl = 0;
    int firstj = 0;
    unsigned lt = (1u << lane) - 1u;
    for (int base = 0; base < NN; base += 32) {
        int j = base + lane;
        float a = (j < NN) ? arow[j] : 0.0f;
        bool nz = (j < NN) && (a != 0.0f);
        bool pl = (j < NN) && (a > 1e-5f);
        unsigned mnz = __ballot_sync(0xffffffffu, nz);
        unsigned mpl = __ballot_sync(0xffffffffu, pl);
        if (nz) {
            int pos = cnz + __popc(mnz & lt);
            g_nz[(size_t)wg * LSTR + pos] =
                ((ull)__float_as_uint(a) << 32) | (unsigned)j;
        }
        if (pl) {
            int pos = cpl + __popc(mpl & lt);
            g_pl_idx[(size_t)wg * LSTR + pos] = j;
        }
        if (cpl == 0 && mpl) firstj = base + __ffs(mpl) - 1;
        cnz += __popc(mnz);
        cpl += __popc(mpl);
    }
    int pnz = (cnz + 7) & ~7;
    int ppl = (cpl + 7) & ~7;
    if (lane < pnz - cnz) g_nz[(size_t)wg * LSTR + cnz + lane] = 0ull;
    if (lane < ppl - cpl) g_pl_idx[(size_t)wg * LSTR + cpl + lane] = firstj;
    if (lane == 0) { g_nz_cnt[wg] = pnz; g_pl_cnt[wg] = ppl; }
}

// ---------------- dense GEMM: double-buffered cp.async, R x 4 tile ----------
// C[m,g] = A[m,:] @ W[:,g] (+bias, relu); m flattened 0..8511.
// grid (8512/(R*RG)), block (G/4, RG). Two smem stages; fills overlap compute.
template<int R>
__global__ void k_dense_db(const float* __restrict__ A, const float* __restrict__ W,
                           const float* __restrict__ bias, float* __restrict__ C,
                           int K, int AS, int G, int GP, int do_relu) {
    const int KC = 32;
    extern __shared__ float sm[];
    int BN = blockDim.x * 4;                 // == G
    int nrows = R * blockDim.y;
    int stageW = KC * BN;
    int stageA = nrows * KC;
    int stride = stageW + stageA;            // floats per stage

    int m0   = blockIdx.x * nrows;
    int tid  = threadIdx.y * blockDim.x + threadIdx.x;
    int nthr = blockDim.x * blockDim.y;
    int g0   = threadIdx.x * 4;
    int nch  = (K + KC - 1) / KC;

    float acc[R][4];
    #pragma unroll
    for (int r = 0; r < R; r++)
        #pragma unroll
        for (int c = 0; c < 4; c++) acc[r][c] = 0.0f;

    // prefetch helper (inlined twice)
    #define PREFETCH(CH, BUF) do {                                              \
        float* pW = sm + (BUF) * stride;                                        \
        float* pA = pW + stageW;                                                \
        int kc = (CH) * KC;                                                     \
        for (int kk = threadIdx.y; kk < KC; kk += blockDim.y) {                 \
            int k = kc + kk;                                                    \
            float* d = pW + kk * BN + g0;                                       \
            if (k < K) cp16(smem_u32p(d), W + (size_t)k * G + g0);              \
            else *reinterpret_cast<float4*>(d) = make_float4(0.f,0.f,0.f,0.f);  \
        }                                                                       \
        for (int idx = tid; idx < stageA; idx += nthr) {                        \
            int r = idx >> 5, kk = idx & 31;                                    \
            int k = kc + kk;                                                    \
            if (k < K) cp4(smem_u32p(pA + idx), A + (size_t)(m0 + r) * AS + k); \
            else pA[idx] = 0.0f;                                                \
        }                                                                       \
    } while (0)

    PREFETCH(0, 0);
    cp_commit();

    for (int ch = 0; ch < nch; ch++) {
        int buf = ch & 1;
        if (ch + 1 < nch) {
            PREFETCH(ch + 1, buf ^ 1);
            cp_commit();
            cp_wait<1>();
        } else {
            cp_wait<0>();
        }
        __syncthreads();

        const float* sW  = sm + buf * stride;
        const float* sAr = sW + stageW + threadIdx.y * R * KC;
        #pragma unroll 8
        for (int kk = 0; kk < KC; kk++) {
            float4 w = *reinterpret_cast<const float4*>(sW + kk * BN + g0);
            #pragma unroll
            for (int r = 0; r < R; r++) {
                float a = sAr[r * KC + kk];          // warp broadcast
                acc[r][0] = fmaf(a, w.x, acc[r][0]);
                acc[r][1] = fmaf(a, w.y, acc[r][1]);
                acc[r][2] = fmaf(a, w.z, acc[r][2]);
                acc[r][3] = fmaf(a, w.w, acc[r][3]);
            }
        }
        __syncthreads();   // protect buf from being refilled before all consume
    }
    #undef PREFETCH

    float4 bv = make_float4(0.f, 0.f, 0.f, 0.f);
    if (bias) bv = *reinterpret_cast<const float4*>(bias + g0);
    int i0 = threadIdx.y * R;
    #pragma unroll
    for (int r = 0; r < R; r++) {
        int row = m0 + i0 + r;
        float4 v = make_float4(acc[r][0] + bv.x, acc[r][1] + bv.y,
                               acc[r][2] + bv.z, acc[r][3] + bv.w);
        if (do_relu) {
            v.x = fmaxf(v.x, 0.f); v.y = fmaxf(v.y, 0.f);
            v.z = fmaxf(v.z, 0.f); v.w = fmaxf(v.w, 0.f);
        }
        *reinterpret_cast<float4*>(C + (size_t)row * GP + g0) = v;
    }
}

// ---------------- spmm + relu, 4 cols/thread, 8-deep gather -----------------
__global__ void k_spmm4(const float* __restrict__ T, const float* __restrict__ bias,
                        float* __restrict__ O, int G) {
    int b = blockIdx.y;
    int i = blockIdx.x * blockDim.y + threadIdx.y;
    if (i >= NN) return;
    int row = b * NN + i;
    int g0 = threadIdx.x * 4;

    int cnt = g_nz_cnt[row];
    const ull* L = g_nz + (size_t)row * LSTR;
    const float* Tb = T + (size_t)b * NN * G + g0;

    ull acc0 = pk2(bias[g0], bias[g0 + 1]);
    ull acc1 = pk2(bias[g0 + 2], bias[g0 + 3]);
    for (int e = 0; e < cnt; e += 8) {
        ull p[8];
        #pragma unroll
        for (int u = 0; u < 8; u++) p[u] = L[e + u];
        ulonglong2 t[8];
        #pragma unroll
        for (int u = 0; u < 8; u++)
            t[u] = *(const ulonglong2*)(Tb + (size_t)(unsigned)p[u] * G);
        #pragma unroll
        for (int u = 0; u < 8; u++) {
            float v = __uint_as_float((unsigned)(p[u] >> 32));
            ull v2 = pk2(v, v);
            FMA2(acc0, t[u].x, v2);
            FMA2(acc1, t[u].y, v2);
        }
    }
    float h0, h1, h2, h3;
    upk2(acc0, h0, h1);
    upk2(acc1, h2, h3);
    float4 r = make_float4(fmaxf(h0, 0.f), fmaxf(h1, 0.f), fmaxf(h2, 0.f), fmaxf(h3, 0.f));
    *reinterpret_cast<float4*>(O + (size_t)row * G + g0) = r;
}

// ---------------- neighbor max-pool, 4 cols/thread, 8-deep ------------------
__global__ void k_pool4(const float* __restrict__ H, float* __restrict__ O, int G) {
    int b = blockIdx.y;
    int i = blockIdx.x * blockDim.y + threadIdx.y;
    if (i >= NN) return;
    int row = b * NN + i;
    int g0 = threadIdx.x * 4;

    int cnt = g_pl_cnt[row];
    const int* ji = g_pl_idx + (size_t)row * LSTR;
    const float4* Hb = reinterpret_cast<const float4*>(H + (size_t)b * NN * G + g0);
    int pitch = G >> 2;

    float4 m = make_float4(0.f, 0.f, 0.f, 0.f);
    for (int e = 0; e < cnt; e += 8) {
        int j[8];
        #pragma unroll
        for (int u = 0; u < 8; u++) j[u] = ji[e + u];
        float4 h[8];
        #pragma unroll
        for (int u = 0; u < 8; u++) h[u] = Hb[(size_t)j[u] * pitch];
        #pragma unroll
        for (int u = 0; u < 8; u++) {
            m.x = fmaxf(m.x, h[u].x);
            m.y = fmaxf(m.y, h[u].y);
            m.z = fmaxf(m.z, h[u].z);
            m.w = fmaxf(m.w, h[u].w);
        }
    }
    reinterpret_cast<float4*>(O + (size_t)row * G + g0)[0] = m;
}

// ---------------- head: gc4 + fc1 + fin + sigmoid ----------
__global__ void k_final(const float* __restrict__ P3,
                        const float* __restrict__ gc4_w,
                        const float* __restrict__ gc4_b,
                        const float* __restrict__ fc1_w,
                        const float* __restrict__ fc1_b,
                        const float* __restrict__ fin_w,
                        const float* __restrict__ fin_b,
                        float* __restrict__ out) {
    int b = blockIdx.x;
    int t = threadIdx.x;
    __shared__ float t4[NN];
    __shared__ float h[NN];
    __shared__ float rr[3];

    if (t < NN) {
        const float* p = P3 + (size_t)(b * NN + t) * GP3;
        float a = 0.0f;
        #pragma unroll
        for (int k = 0; k < F0; k++) a = fmaf(p[k], gc4_w[k], a);
        t4[t] = a;
    }
    __syncthreads();

    if (t < NN) {
        int row = b * NN + t;
        int cnt = g_nz_cnt[row];
        const ull* L = g_nz + (size_t)row * LSTR;
        float acc = gc4_b[0];
        for (int e = 0; e < cnt; e++) {
            ull p = L[e];
            acc = fmaf(__uint_as_float((unsigned)(p >> 32)), t4[(int)(unsigned)p], acc);
        }
        h[t] = fmaxf(acc, 0.0f);
    }
    __syncthreads();

    if (t < 3) {
        float a = fc1_b[t];
        for (int k = 0; k < NN - 1; k++)
            a = fmaf(h[k + 1], fc1_w[k * 3 + t], a);
        rr[t] = a;
    }
    __syncthreads();

    if (t == 0) {
        float z = h[0] * fin_w[0] + rr[0] * fin_w[1] + rr[1] * fin_w[2]
                + rr[2] * fin_w[3] + fin_b[0];
        out[b] = 1.0f / (1.0f + expf(-z));
    }
}

// ---------------- launch ----------------
extern "C" void kernel_launch(void* const* d_in, const int* in_sizes, int n_in,
                              void* d_out, int out_size) {
    const float* x     = (const float*)d_in[0];
    const float* adj   = (const float*)d_in[1];
    const float* emb_w = (const float*)d_in[2];
    const float* emb_b = (const float*)d_in[3];
    const float* gc1_w = (const float*)d_in[4];
    const float* gc1_b = (const float*)d_in[5];
    const float* gc2_w = (const float*)d_in[6];
    const float* gc2_b = (const float*)d_in[7];
    const float* gc3_w = (const float*)d_in[8];
    const float* gc3_b = (const float*)d_in[9];
    const float* gc4_w = (const float*)d_in[10];
    const float* gc4_b = (const float*)d_in[11];
    const float* fc1_w = (const float*)d_in[12];
    const float* fc1_b = (const float*)d_in[13];
    const float* fin_w = (const float*)d_in[14];
    const float* fin_b = (const float*)d_in[15];
    float* out = (float*)d_out;

    float *dA, *dB, *dEw, *dEb, *d3w, *db3;
    cudaGetSymbolAddress((void**)&dA,  g_bufA);
    cudaGetSymbolAddress((void**)&dB,  g_bufB);
    cudaGetSymbolAddress((void**)&dEw, g_embw);
    cudaGetSymbolAddress((void**)&dEb, g_embb);
    cudaGetSymbolAddress((void**)&d3w, g_gc3w);
    cudaGetSymbolAddress((void**)&db3, g_b3pad);

    cudaFuncSetAttribute(k_dense_db<4>,
                         cudaFuncAttributeMaxDynamicSharedMemorySize, 75776);

    // 0a) pad weights
    k_pad<<<(PAD_T3 + 255) / 256, 256>>>(emb_w, emb_b, gc3_w, gc3_b);
    // 0b) sparse lists (8-padded)
    {
        int warps_per_blk = 8;
        int blocks = (NROW + warps_per_blk - 1) / warps_per_blk;
        k_build_lists<<<blocks, warps_per_blk * 32>>>(adj);
    }

    const int KC = 32;
    // smem bytes: 2 stages of (KC*G + nrows*KC)
    int sm_emb = 2 * (KC * GP1 + 32 * KC) * 4;   // 47104
    int sm_gc1 = 2 * (KC * H1  + 32 * KC) * 4;   // 73728
    int sm_gc2 = 2 * (KC * H2  + 64 * KC) * 4;   // 49152
    int sm_gc3 = 2 * (KC * GP3 + 64 * KC) * 4;   // 35840

    // 1) emb: dA = relu(x @ embw_pad + embb_pad)   [8512,152]
    k_dense_db<4><<<266, dim3(38, 8), sm_emb>>>(x, dEw, dEb, dA, F0, F0, GP1, GP1, 1);
    // 2) dB = dA @ gc1_w                           [8512,256] (A stride 152, K=150)
    k_dense_db<4><<<266, dim3(64, 8), sm_gc1>>>(dA, gc1_w, nullptr, dB, F1, GP1, H1, H1, 0);
    // 3) dA = relu(adj.dB + gc1_b)
    k_spmm4<<<dim3(34, BB), dim3(64, 4)>>>(dB, gc1_b, dA, H1);
    // 4) dB = pool(dA)
    k_pool4<<<dim3(34, BB), dim3(64, 4)>>>(dA, dB, H1);
    // 5) dA = dB @ gc2_w                           [8512,128]
    k_dense_db<4><<<133, dim3(32, 16), sm_gc2>>>(dB, gc2_w, nullptr, dA, H1, H1, H2, H2, 0);
    // 6) dB = relu(adj.dA + gc2_b)
    k_spmm4<<<dim3(17, BB), dim3(32, 8)>>>(dA, gc2_b, dB, H2);
    // 7) dA = pool(dB)
    k_pool4<<<dim3(17, BB), dim3(32, 8)>>>(dB, dA, H2);
    // 8) dB = dA @ gc3w_pad                        [8512,76]
    k_dense_db<4><<<133, dim3(19, 16), sm_gc3>>>(dA, d3w, nullptr, dB, H2, H2, GP3, GP3, 0);
    // 9) dA = relu(adj.dB + b3pad)                 [.,76]
    k_spmm4<<<dim3(17, BB), dim3(19, 8)>>>(dB, db3, dA, GP3);
    // 10) dB = pool(dA)                            [.,76]
    k_pool4<<<dim3(17, BB), dim3(19, 8)>>>(dA, dB, GP3);
    // 11) head
    k_final<<<BB, 160>>>(dB, gc4_w, gc4_b, fc1_w, fc1_b, fin_w, fin_b, out);
}